// round 12
// baseline (speedup 1.0000x reference)
#include <cuda_runtime.h>
#include <cuda_fp16.h>
#include <math.h>

#define OUT_F 512
#define IN_F  1024
#define BATCH 256
#define NPAIR 128          // batch pairs (2 rows per half2 lane)
#define NSPLIT 32          // i-splits of 32 inputs each
#define JTILE  32          // output nodes per reduce block
#define MSTR   36          // Ms row stride (u32): conflict-free + 16B aligned

// Scratch (device globals — no allocation allowed anywhere)
__device__ unsigned g_Xt[IN_F * NPAIR];          // x transposed+packed half2-as-u32: [i*128+p] = (x[2p][i], x[2p+1][i])
__device__ __half2  g_P[NSPLIT * OUT_F * NPAIR]; // partial reductions [s][j][p]

static __device__ __forceinline__ __half2 u2h2(unsigned v) {
    return *reinterpret_cast<__half2*>(&v);
}

// Hard gumbel argmax decision -> 32-bit select mask.
// g(u) = -log(-log(u+eps)+eps) is strictly increasing, so for c0 == c1 the
// argmax is exactly (u1 > u0); ties -> index 0 = edge, matching jnp.argmax.
// General-c fallback keeps the bit-verified logf path.
static __device__ __forceinline__ unsigned edge_mask(float c0, float c1,
                                                     float u0, float u1)
{
    bool no_edge;
    if (c0 == c1) {
        no_edge = u1 > u0;
    } else {
        const float eps = 1e-10f;
        float g0 = -logf(-logf(u0 + eps) + eps);
        float g1 = -logf(-logf(u1 + eps) + eps);
        no_edge = (c1 + g1) > (c0 + g0);
    }
    return no_edge ? 0xFFFFFFFFu : 0u;
}

// ---------------------------------------------------------------------------
// Kernel 1: transpose/pack x into half2 [i][pair]. 1.5 MB total traffic.
// ---------------------------------------------------------------------------
__global__ __launch_bounds__(256) void pack_x_kernel(const float* __restrict__ x)
{
    __shared__ float ts[64][33];
    const int tid = threadIdx.x;
    const int it = blockIdx.x & 31, bt = blockIdx.x >> 5;
    const int i0 = it * 32, b0 = bt * 64;
    const int col = tid & 31, rw = tid >> 5;
    #pragma unroll
    for (int k = 0; k < 8; k++)
        ts[rw + k * 8][col] = x[(b0 + rw + k * 8) * IN_F + i0 + col];   // coalesced
    __syncthreads();
    #pragma unroll
    for (int k = 0; k < 4; k++) {
        int idx = tid + k * 256;                  // 0..1023
        int il = idx >> 5, pl = idx & 31;
        __half2 h = __floats2half2_rn(ts[2 * pl + 0][il], ts[2 * pl + 1][il]);
        g_Xt[(i0 + il) * NPAIR + (b0 >> 1) + pl] = *reinterpret_cast<unsigned*>(&h);
    }
}

// ---------------------------------------------------------------------------
// Kernel 2 (fused mask + reduce): each block owns a disjoint 32j x 32i tile of
// the edge decision, so it computes its masks inline from etc/noise (4+4
// float4 loads per thread -> MLP=8, overlapped with compute across blocks)
// and never materializes them in global memory.
// Inner loop per half2: 1 LOP3 (alu pipe) + 1 HMNMX2 (fma pipe). Select
// constant is the EXACT reference no-edge offset (2.0 / -1.0) -> no clamp.
// ---------------------------------------------------------------------------
__global__ __launch_bounds__(128) void reduce_kernel(
    const float* __restrict__ etc, const float* __restrict__ noise)
{
    __shared__ unsigned Ms[JTILE][MSTR];  // mask tile [j][i], padded rows

    const int s  = blockIdx.x;            // 0..31
    const int jt = blockIdx.y;            // 0..15
    const int i0 = s * 32;
    const int j0 = jt * JTILE;
    const int t  = threadIdx.x;           // batch-pair index for the main loop

    // --- Inline mask build: thread (jl = t/4, c = t%4) handles 8 elements ---
    {
        const int jl = t >> 2, c = t & 3;
        const size_t rb = ((size_t)(j0 + jl) * IN_F + i0) * 2;   // float offset of row
        const float4* ep = reinterpret_cast<const float4*>(etc   + rb) + 4 * c;
        const float4* np = reinterpret_cast<const float4*>(noise + rb) + 4 * c;
        float4 e[4], n[4];
        #pragma unroll
        for (int q = 0; q < 4; q++) { e[q] = ep[q]; n[q] = np[q]; }  // MLP=8
        #pragma unroll
        for (int q = 0; q < 4; q++) {
            Ms[jl][8 * c + 2 * q + 0] = edge_mask(e[q].x, e[q].y, n[q].x, n[q].y);
            Ms[jl][8 * c + 2 * q + 1] = edge_mask(e[q].z, e[q].w, n[q].z, n[q].w);
        }
    }

    // Cache this pair's 32 x values in registers (reused across all 32 j)
    unsigned xr[32];
    #pragma unroll
    for (int k = 0; k < 32; k++)
        xr[k] = g_Xt[(i0 + k) * NPAIR + t];          // 128B coalesced per warp
    __syncthreads();

    const unsigned OFFP = 0x40004000u;               // half2(+2.0) : min-node no-edge value
    const unsigned OFFN = 0xBC00BC00u;               // half2(-1.0) : max-node no-edge value
    const __half2 PI = u2h2(OFFP);                   // min identity == masked value
    const __half2 NI = u2h2(OFFN);                   // max identity == masked value

    // (min-node, max-node) pairs; jj even -> global j even -> t-norm (min)
    #pragma unroll 1
    for (int jj = 0; jj < JTILE; jj += 2) {
        __half2 m0 = PI, m1 = PI;                    // 4 chains for ILP
        __half2 M0 = NI, M1 = NI;
        const uint4* a0p = reinterpret_cast<const uint4*>(&Ms[jj][0]);      // 144B rows: 16B aligned
        const uint4* a1p = reinterpret_cast<const uint4*>(&Ms[jj + 1][0]);
        #pragma unroll
        for (int q = 0; q < 8; q++) {
            uint4 a0 = a0p[q];                       // LDS.128 uniform -> broadcast
            uint4 a1 = a1p[q];
            m0 = __hmin2(m0, u2h2((a0.x & OFFP) | (~a0.x & xr[4 * q + 0])));  // LOP3 + HMNMX2
            m1 = __hmin2(m1, u2h2((a0.y & OFFP) | (~a0.y & xr[4 * q + 1])));
            m0 = __hmin2(m0, u2h2((a0.z & OFFP) | (~a0.z & xr[4 * q + 2])));
            m1 = __hmin2(m1, u2h2((a0.w & OFFP) | (~a0.w & xr[4 * q + 3])));
            M0 = __hmax2(M0, u2h2((a1.x & OFFN) | (~a1.x & xr[4 * q + 0])));
            M1 = __hmax2(M1, u2h2((a1.y & OFFN) | (~a1.y & xr[4 * q + 1])));
            M0 = __hmax2(M0, u2h2((a1.z & OFFN) | (~a1.z & xr[4 * q + 2])));
            M1 = __hmax2(M1, u2h2((a1.w & OFFN) | (~a1.w & xr[4 * q + 3])));
        }
        g_P[(s * OUT_F + j0 + jj + 0) * NPAIR + t] = __hmin2(m0, m1);  // coalesced
        g_P[(s * OUT_F + j0 + jj + 1) * NPAIR + t] = __hmax2(M0, M1);
    }
}

// ---------------------------------------------------------------------------
// Kernel 3: combine the NSPLIT partials (packed), unpack to fp32. No clamp
// needed: masked lanes already carry the exact identity offsets.
// ---------------------------------------------------------------------------
__global__ __launch_bounds__(256) void combine_kernel(float* __restrict__ out)
{
    int g = blockIdx.x * blockDim.x + threadIdx.x;   // 65536 threads
    int j = g >> 7;                                  // 0..511 (warp-uniform)
    int p = g & (NPAIR - 1);
    if ((j & 1) == 0) {
        __half2 acc = __float2half2_rn(2.0f);
        #pragma unroll
        for (int s = 0; s < NSPLIT; s++)
            acc = __hmin2(acc, g_P[(s * OUT_F + j) * NPAIR + p]);
        out[(2 * p + 0) * OUT_F + j] = __low2float(acc);
        out[(2 * p + 1) * OUT_F + j] = __high2float(acc);
    } else {
        __half2 acc = __float2half2_rn(-1.0f);
        #pragma unroll
        for (int s = 0; s < NSPLIT; s++)
            acc = __hmax2(acc, g_P[(s * OUT_F + j) * NPAIR + p]);
        out[(2 * p + 0) * OUT_F + j] = __low2float(acc);
        out[(2 * p + 1) * OUT_F + j] = __high2float(acc);
    }
}

// ---------------------------------------------------------------------------
extern "C" void kernel_launch(void* const* d_in, const int* in_sizes, int n_in,
                              void* d_out, int out_size)
{
    const float* x     = (const float*)d_in[0];   // [256, 1024]
    const float* etc   = (const float*)d_in[1];   // [512, 1024, 2]
    const float* noise = (const float*)d_in[2];   // [512, 1024, 2]
    float* out = (float*)d_out;                   // [256, 512]

    pack_x_kernel<<<128, 256>>>(x);
    reduce_kernel<<<dim3(NSPLIT, OUT_F / JTILE), 128>>>(etc, noise);
    combine_kernel<<<(OUT_F * NPAIR + 255) / 256, 256>>>(out);
}

// round 13
// speedup vs baseline: 1.0262x; 1.0262x over previous
#include <cuda_runtime.h>
#include <cuda_fp16.h>
#include <math.h>

#define OUT_F 512
#define IN_F  1024
#define BATCH 256
#define NPAIR 128          // batch pairs (2 rows per half2 lane)
#define NSPLIT 32          // i-splits of 32 inputs each
#define JTILE  32          // output nodes per reduce block
#define MSTR   36          // Ms row stride (u32): conflict-free + 16B aligned

// Scratch (device global — no allocation allowed anywhere)
__device__ __half2 g_P[NSPLIT * OUT_F * NPAIR];  // partial reductions [s][j][p]

static __device__ __forceinline__ __half2 u2h2(unsigned v) {
    return *reinterpret_cast<__half2*>(&v);
}

// Hard gumbel argmax decision -> 32-bit select mask.
// g(u) = -log(-log(u+eps)+eps) is strictly increasing, so for c0 == c1 the
// argmax is exactly (u1 > u0); ties -> index 0 = edge, matching jnp.argmax.
// General-c fallback keeps the bit-verified logf path.
static __device__ __forceinline__ unsigned edge_mask(float c0, float c1,
                                                     float u0, float u1)
{
    bool no_edge;
    if (c0 == c1) {
        no_edge = u1 > u0;
    } else {
        const float eps = 1e-10f;
        float g0 = -logf(-logf(u0 + eps) + eps);
        float g1 = -logf(-logf(u1 + eps) + eps);
        no_edge = (c1 + g1) > (c0 + g0);
    }
    return no_edge ? 0xFFFFFFFFu : 0u;
}

// ---------------------------------------------------------------------------
// Kernel 1 (fully fused): mask build + x stage/pack + select-min/max reduce.
// Block (s, jt) owns the disjoint tile (j0..j0+31) x (i0..i0+31):
//   - computes its 1024 edge decisions inline from etc/noise (8 float4
//     loads/thread, MLP=8) -> Ms in SMEM
//   - stages x[:, i0..i0+31] via coalesced 128B row reads -> packs 32 half2
//     registers per thread (pair p = rows 2p, 2p+1)
//   - inner loop per half2: 1 LOP3 (alu pipe) + 1 HMNMX2 (fma pipe), select
//     constant = EXACT reference no-edge offset (2.0 / -1.0) -> no clamp.
// All 512 blocks are co-resident: staging L2 traffic overlaps compute.
// ---------------------------------------------------------------------------
__global__ __launch_bounds__(128) void reduce_kernel(
    const float* __restrict__ etc, const float* __restrict__ noise,
    const float* __restrict__ x)
{
    __shared__ unsigned Ms[JTILE][MSTR];   // mask tile [j][i], padded rows
    __shared__ float    xsf[32][257];      // x slice transposed [i][b], padded

    const int s  = blockIdx.x;             // 0..31
    const int jt = blockIdx.y;             // 0..15
    const int i0 = s * 32;
    const int j0 = jt * JTILE;
    const int t  = threadIdx.x;            // batch-pair index for the main loop
    const int li = t & 31;
    const int w  = t >> 5;

    // --- Phase A: stage x slice (coalesced 128B per row; 64 rows per warp) ---
    #pragma unroll
    for (int k = 0; k < 64; k++) {
        int b = w * 64 + k;
        xsf[li][b] = x[b * IN_F + i0 + li];
    }

    // --- Phase B: inline mask build: thread (jl = t/4, c = t%4), 8 elements ---
    {
        const int jl = t >> 2, c = t & 3;
        const size_t rb = ((size_t)(j0 + jl) * IN_F + i0) * 2;   // float offset of row
        const float4* ep = reinterpret_cast<const float4*>(etc   + rb) + 4 * c;
        const float4* np = reinterpret_cast<const float4*>(noise + rb) + 4 * c;
        float4 e[4], n[4];
        #pragma unroll
        for (int q = 0; q < 4; q++) { e[q] = ep[q]; n[q] = np[q]; }  // MLP=8
        #pragma unroll
        for (int q = 0; q < 4; q++) {
            Ms[jl][8 * c + 2 * q + 0] = edge_mask(e[q].x, e[q].y, n[q].x, n[q].y);
            Ms[jl][8 * c + 2 * q + 1] = edge_mask(e[q].z, e[q].w, n[q].z, n[q].w);
        }
    }
    __syncthreads();

    // Pack this pair's 32 x values into half2 registers (reused across all 32 j)
    unsigned xr[32];
    #pragma unroll
    for (int k = 0; k < 32; k++) {
        __half2 h = __floats2half2_rn(xsf[k][2 * t], xsf[k][2 * t + 1]);
        xr[k] = *reinterpret_cast<unsigned*>(&h);
    }

    const unsigned OFFP = 0x40004000u;               // half2(+2.0) : min-node no-edge value
    const unsigned OFFN = 0xBC00BC00u;               // half2(-1.0) : max-node no-edge value
    const __half2 PI = u2h2(OFFP);                   // min identity == masked value
    const __half2 NI = u2h2(OFFN);                   // max identity == masked value

    // (min-node, max-node) pairs; jj even -> global j even -> t-norm (min)
    #pragma unroll 1
    for (int jj = 0; jj < JTILE; jj += 2) {
        __half2 m0 = PI, m1 = PI;                    // 4 chains for ILP
        __half2 M0 = NI, M1 = NI;
        const uint4* a0p = reinterpret_cast<const uint4*>(&Ms[jj][0]);      // 144B rows: 16B aligned
        const uint4* a1p = reinterpret_cast<const uint4*>(&Ms[jj + 1][0]);
        #pragma unroll
        for (int q = 0; q < 8; q++) {
            uint4 a0 = a0p[q];                       // LDS.128 uniform -> broadcast
            uint4 a1 = a1p[q];
            m0 = __hmin2(m0, u2h2((a0.x & OFFP) | (~a0.x & xr[4 * q + 0])));  // LOP3 + HMNMX2
            m1 = __hmin2(m1, u2h2((a0.y & OFFP) | (~a0.y & xr[4 * q + 1])));
            m0 = __hmin2(m0, u2h2((a0.z & OFFP) | (~a0.z & xr[4 * q + 2])));
            m1 = __hmin2(m1, u2h2((a0.w & OFFP) | (~a0.w & xr[4 * q + 3])));
            M0 = __hmax2(M0, u2h2((a1.x & OFFN) | (~a1.x & xr[4 * q + 0])));
            M1 = __hmax2(M1, u2h2((a1.y & OFFN) | (~a1.y & xr[4 * q + 1])));
            M0 = __hmax2(M0, u2h2((a1.z & OFFN) | (~a1.z & xr[4 * q + 2])));
            M1 = __hmax2(M1, u2h2((a1.w & OFFN) | (~a1.w & xr[4 * q + 3])));
        }
        g_P[(s * OUT_F + j0 + jj + 0) * NPAIR + t] = __hmin2(m0, m1);  // coalesced
        g_P[(s * OUT_F + j0 + jj + 1) * NPAIR + t] = __hmax2(M0, M1);
    }
}

// ---------------------------------------------------------------------------
// Kernel 2: combine the NSPLIT partials (packed), unpack to fp32. No clamp
// needed: masked lanes already carry the exact identity offsets.
// ---------------------------------------------------------------------------
__global__ __launch_bounds__(256) void combine_kernel(float* __restrict__ out)
{
    int g = blockIdx.x * blockDim.x + threadIdx.x;   // 65536 threads
    int j = g >> 7;                                  // 0..511 (warp-uniform)
    int p = g & (NPAIR - 1);
    if ((j & 1) == 0) {
        __half2 acc = __float2half2_rn(2.0f);
        #pragma unroll
        for (int s = 0; s < NSPLIT; s++)
            acc = __hmin2(acc, g_P[(s * OUT_F + j) * NPAIR + p]);
        out[(2 * p + 0) * OUT_F + j] = __low2float(acc);
        out[(2 * p + 1) * OUT_F + j] = __high2float(acc);
    } else {
        __half2 acc = __float2half2_rn(-1.0f);
        #pragma unroll
        for (int s = 0; s < NSPLIT; s++)
            acc = __hmax2(acc, g_P[(s * OUT_F + j) * NPAIR + p]);
        out[(2 * p + 0) * OUT_F + j] = __low2float(acc);
        out[(2 * p + 1) * OUT_F + j] = __high2float(acc);
    }
}

// ---------------------------------------------------------------------------
extern "C" void kernel_launch(void* const* d_in, const int* in_sizes, int n_in,
                              void* d_out, int out_size)
{
    const float* x     = (const float*)d_in[0];   // [256, 1024]
    const float* etc   = (const float*)d_in[1];   // [512, 1024, 2]
    const float* noise = (const float*)d_in[2];   // [512, 1024, 2]
    float* out = (float*)d_out;                   // [256, 512]

    reduce_kernel<<<dim3(NSPLIT, OUT_F / JTILE), 128>>>(etc, noise, x);
    combine_kernel<<<(OUT_F * NPAIR + 255) / 256, 256>>>(out);
}

// round 14
// speedup vs baseline: 1.0450x; 1.0183x over previous
#include <cuda_runtime.h>
#include <cuda_fp16.h>
#include <math.h>

#define OUT_F 512
#define IN_F  1024
#define BATCH 256
#define NPAIR 128          // batch pairs (2 rows per half2 lane)
#define NSPLIT 8           // i-splits of 128 inputs each (4 x 32 sub-slices)
#define JTILE  16          // output nodes per reduce block
#define MSTR   36          // Ms row stride (u32): conflict-free + 16B aligned

// Scratch (device global — no allocation allowed anywhere)
__device__ __half2 g_P[NSPLIT * OUT_F * NPAIR];  // partial reductions [s][j][p]

static __device__ __forceinline__ __half2 u2h2(unsigned v) {
    return *reinterpret_cast<__half2*>(&v);
}
static __device__ __forceinline__ unsigned h2u(__half2 h) {
    return *reinterpret_cast<unsigned*>(&h);
}

// Hard gumbel argmax decision -> 32-bit select mask.
// g(u) = -log(-log(u+eps)+eps) is strictly increasing, so for c0 == c1 the
// argmax is exactly (u1 > u0); ties -> index 0 = edge, matching jnp.argmax.
// General-c fallback keeps the bit-verified logf path.
static __device__ __forceinline__ unsigned edge_mask(float c0, float c1,
                                                     float u0, float u1)
{
    bool no_edge;
    if (c0 == c1) {
        no_edge = u1 > u0;
    } else {
        const float eps = 1e-10f;
        float g0 = -logf(-logf(u0 + eps) + eps);
        float g1 = -logf(-logf(u1 + eps) + eps);
        no_edge = (c1 + g1) > (c0 + g0);
    }
    return no_edge ? 0xFFFFFFFFu : 0u;
}

// ---------------------------------------------------------------------------
// Kernel 1 (fused): mask build + x stage/pack + select-min/max reduce.
// Block (s, jt) owns (j0..j0+15) x (s*128..s*128+127), processed as four
// 32-input sub-slices with persistent register accumulators:
//   - per sub-slice: stage x (coalesced 128B rows), build the 16x32 edge
//     masks inline from etc/noise (2+2 float4 per thread), pack 32 half2 regs
//   - inner loop per half2: 1 LOP3 (alu pipe) + 1 HMNMX2 (fma pipe); select
//     constant = EXACT reference no-edge offset (2.0 / -1.0) -> no clamp.
// Grid 8x32 = 256 blocks (1024 warps): one co-resident wave, staging overlaps.
// ---------------------------------------------------------------------------
__global__ __launch_bounds__(128) void reduce_kernel(
    const float* __restrict__ etc, const float* __restrict__ noise,
    const float* __restrict__ x)
{
    __shared__ unsigned Ms[JTILE][MSTR];   // mask tile [j][i], padded rows
    __shared__ float    xsf[32][257];      // x sub-slice transposed [i][b], padded

    const int s  = blockIdx.x;             // 0..7
    const int jt = blockIdx.y;             // 0..31
    const int j0 = jt * JTILE;
    const int t  = threadIdx.x;            // batch-pair index for the main loop
    const int li = t & 31;
    const int w  = t >> 5;

    const unsigned OFFP = 0x40004000u;     // half2(+2.0) : min-node no-edge value
    const unsigned OFFN = 0xBC00BC00u;     // half2(-1.0) : max-node no-edge value
    const __half2 PI = u2h2(OFFP);         // min identity == masked value
    const __half2 NI = u2h2(OFFN);         // max identity == masked value

    // Persistent accumulators: 8 (min,max) node pairs x 2 ILP chains
    __half2 m0a[JTILE / 2], m1a[JTILE / 2], M0a[JTILE / 2], M1a[JTILE / 2];
    #pragma unroll
    for (int p = 0; p < JTILE / 2; p++) {
        m0a[p] = PI; m1a[p] = PI; M0a[p] = NI; M1a[p] = NI;
    }

    #pragma unroll 1
    for (int sub = 0; sub < 4; sub++) {
        const int i0 = s * 128 + sub * 32;

        if (sub) __syncthreads();          // protect smem reuse

        // Stage x sub-slice: warp w loads rows w*64..w*64+63, 128B coalesced
        #pragma unroll
        for (int k = 0; k < 64; k++) {
            int b = w * 64 + k;
            xsf[li][b] = x[b * IN_F + i0 + li];
        }

        // Inline mask build: thread (jl = t/8, c = t%8) handles 4 elements
        {
            const int jl = t >> 3, c = t & 7;
            const size_t rb = ((size_t)(j0 + jl) * IN_F + i0) * 2;  // float offset
            const float4* ep = reinterpret_cast<const float4*>(etc   + rb) + 2 * c;
            const float4* np = reinterpret_cast<const float4*>(noise + rb) + 2 * c;
            float4 e0 = ep[0], e1 = ep[1];
            float4 n0 = np[0], n1 = np[1];
            uint4 mm;
            mm.x = edge_mask(e0.x, e0.y, n0.x, n0.y);
            mm.y = edge_mask(e0.z, e0.w, n0.z, n0.w);
            mm.z = edge_mask(e1.x, e1.y, n1.x, n1.y);
            mm.w = edge_mask(e1.z, e1.w, n1.z, n1.w);
            *reinterpret_cast<uint4*>(&Ms[jl][4 * c]) = mm;   // 16B aligned
        }
        __syncthreads();

        // Pack this pair's 32 x values into half2 registers
        unsigned xr[32];
        #pragma unroll
        for (int k = 0; k < 32; k++)
            xr[k] = h2u(__floats2half2_rn(xsf[k][2 * t], xsf[k][2 * t + 1]));

        // (min-node, max-node) pairs; j0 even -> jj even -> t-norm (min)
        #pragma unroll
        for (int jj = 0; jj < JTILE; jj += 2) {
            __half2 m0 = m0a[jj >> 1], m1 = m1a[jj >> 1];
            __half2 M0 = M0a[jj >> 1], M1 = M1a[jj >> 1];
            const uint4* a0p = reinterpret_cast<const uint4*>(&Ms[jj][0]);
            const uint4* a1p = reinterpret_cast<const uint4*>(&Ms[jj + 1][0]);
            #pragma unroll
            for (int q = 0; q < 8; q++) {
                uint4 a0 = a0p[q];                   // LDS.128 uniform -> broadcast
                uint4 a1 = a1p[q];
                m0 = __hmin2(m0, u2h2((a0.x & OFFP) | (~a0.x & xr[4 * q + 0])));
                m1 = __hmin2(m1, u2h2((a0.y & OFFP) | (~a0.y & xr[4 * q + 1])));
                m0 = __hmin2(m0, u2h2((a0.z & OFFP) | (~a0.z & xr[4 * q + 2])));
                m1 = __hmin2(m1, u2h2((a0.w & OFFP) | (~a0.w & xr[4 * q + 3])));
                M0 = __hmax2(M0, u2h2((a1.x & OFFN) | (~a1.x & xr[4 * q + 0])));
                M1 = __hmax2(M1, u2h2((a1.y & OFFN) | (~a1.y & xr[4 * q + 1])));
                M0 = __hmax2(M0, u2h2((a1.z & OFFN) | (~a1.z & xr[4 * q + 2])));
                M1 = __hmax2(M1, u2h2((a1.w & OFFN) | (~a1.w & xr[4 * q + 3])));
            }
            m0a[jj >> 1] = m0; m1a[jj >> 1] = m1;
            M0a[jj >> 1] = M0; M1a[jj >> 1] = M1;
        }
    }

    // Emit partials (coalesced)
    #pragma unroll
    for (int jj = 0; jj < JTILE; jj += 2) {
        g_P[(s * OUT_F + j0 + jj + 0) * NPAIR + t] = __hmin2(m0a[jj >> 1], m1a[jj >> 1]);
        g_P[(s * OUT_F + j0 + jj + 1) * NPAIR + t] = __hmax2(M0a[jj >> 1], M1a[jj >> 1]);
    }
}

// ---------------------------------------------------------------------------
// Kernel 2: combine the NSPLIT=8 partials (packed), unpack to fp32. No clamp
// needed: masked lanes already carry the exact identity offsets.
// ---------------------------------------------------------------------------
__global__ __launch_bounds__(256) void combine_kernel(float* __restrict__ out)
{
    int g = blockIdx.x * blockDim.x + threadIdx.x;   // 65536 threads
    int j = g >> 7;                                  // 0..511 (warp-uniform)
    int p = g & (NPAIR - 1);
    if ((j & 1) == 0) {
        __half2 acc = __float2half2_rn(2.0f);
        #pragma unroll
        for (int s = 0; s < NSPLIT; s++)
            acc = __hmin2(acc, g_P[(s * OUT_F + j) * NPAIR + p]);
        out[(2 * p + 0) * OUT_F + j] = __low2float(acc);
        out[(2 * p + 1) * OUT_F + j] = __high2float(acc);
    } else {
        __half2 acc = __float2half2_rn(-1.0f);
        #pragma unroll
        for (int s = 0; s < NSPLIT; s++)
            acc = __hmax2(acc, g_P[(s * OUT_F + j) * NPAIR + p]);
        out[(2 * p + 0) * OUT_F + j] = __low2float(acc);
        out[(2 * p + 1) * OUT_F + j] = __high2float(acc);
    }
}

// ---------------------------------------------------------------------------
extern "C" void kernel_launch(void* const* d_in, const int* in_sizes, int n_in,
                              void* d_out, int out_size)
{
    const float* x     = (const float*)d_in[0];   // [256, 1024]
    const float* etc   = (const float*)d_in[1];   // [512, 1024, 2]
    const float* noise = (const float*)d_in[2];   // [512, 1024, 2]
    float* out = (float*)d_out;                   // [256, 512]

    reduce_kernel<<<dim3(NSPLIT, OUT_F / JTILE), 128>>>(etc, noise, x);
    combine_kernel<<<(OUT_F * NPAIR + 255) / 256, 256>>>(out);
}